// round 6
// baseline (speedup 1.0000x reference)
#include <cuda_runtime.h>
#include <cstdint>

#define Bn 256
#define Tn 1024
#define Cn 256
#define Ln 128
#define NPER 256          // 256 periods x 4 steps: t = 4p+1 .. 4p+4 (last guarded)
#define RING 12
#define NEGF (-1e30f)
#define EPSF (1e-7f)
#define NTH 224           // 7 warps
#define LN2F 0.6931471805599453f
#define ESENT (-(1 << 28))

// Roles (one rec warp per SMSP):
//   tid   0..127 : recurrence; thread k owns states 2k,2k+1; K=4 steps/barrier.
//                  Inter-period state = (mantissa float, int exponent): alpha = lin*2^e.
//                  Intra-period arithmetic is pure linear fp32 (no MUFU anywhere).
//   tid 128..159 : per-row denominator sums + blank-emission capture
//   tid 160..223 : cp.async loaders (64 x 16B = 1KB row), 4 rows/period
// State 256 excluded from recurrence; reconstructed in epilogue (validated R4/R5).

__device__ __forceinline__ float ex2f(float x){ float r; asm("ex2.approx.ftz.f32 %0, %1;" : "=f"(r) : "f"(x)); return r; }
__device__ __forceinline__ float lg2f(float x){ float r; asm("lg2.approx.ftz.f32 %0, %1;" : "=f"(r) : "f"(x)); return r; }

// exact 2^d multiply source (d <= 0), clamped: d <= -127 -> 0
__device__ __forceinline__ float sclin(float l, int d){
    d = ::max(d, -127);
    return l * __int_as_float((d + 127) << 23);
}
// pack absolute value x (>=0) into (lin in [1,2), e); zero/denormal -> (0, ESENT)
__device__ __forceinline__ void packv(float x, float& lin, int& e){
    const int bits = __float_as_int(x);
    const int ee = (bits >> 23) & 255;
    if (ee == 0) { lin = 0.f; e = ESENT; }
    else { lin = x * __int_as_float((254 - ee) << 23); e = ee - 127; }
}

__global__ __launch_bounds__(NTH, 2)
void ctc_kernel(const void* __restrict__ yt_raw,
                const float* __restrict__ yp,
                float* __restrict__ out)
{
    __shared__ __align__(16) float ring[RING][Cn];   // 12KB row ring
    __shared__ __align__(16) float4 abuf4[2][132];   // thread k at [k+4]; [0..3] = zero pads
    __shared__ float sums[Tn];
    __shared__ float vbh[Tn];                        // row[t][255] raw
    __shared__ float histL[Tn];                      // A255(t) linear-in-period
    __shared__ float histM[NPER];                    // per-period emax of thread 127
    __shared__ float pre[Tn];
    __shared__ float csum[128], coff[128];
    __shared__ int   labs[132];
    __shared__ float wredA[8], wredB[8], wredC[8];
    __shared__ float PtotS;
    __shared__ int   flag64;

    const int b   = blockIdx.x;
    const int tid = threadIdx.x;
    const float* rowbase = yp + (size_t)b * Tn * Cn;

    if (tid == 0) flag64 = 1;

    // prologue: rows 0..8
    if (tid >= 160) {
        const int lt = tid - 160;
        #pragma unroll
        for (int r = 0; r < 9; ++r) {
            unsigned sa = (unsigned)__cvta_generic_to_shared(&ring[r][lt * 4]);
            const float* g = rowbase + (size_t)r * Cn + lt * 4;
            asm volatile("cp.async.cg.shared.global [%0], [%1], 16;\n" :: "r"(sa), "l"(g));
        }
        asm volatile("cp.async.commit_group;\n");
    }
    __syncthreads();

    if (tid < 128) { if (((const int*)yt_raw)[2 * tid + 1] != 0) flag64 = 0; }
    __syncthreads();

    if (tid < Ln) {
        labs[tid] = flag64 ? (int)((const long long*)yt_raw)[(size_t)b * Ln + tid]
                           : ((const int*)yt_raw)[(size_t)b * Ln + tid];
    }
    if (tid >= Ln && tid < 132) labs[tid] = Cn - 1;
    if (tid >= 132 && tid < 140) {      // zero pads (lin=0, e=ESENT)
        float4 z = { 0.f, __int_as_float(ESENT), 0.f, __int_as_float(ESENT) };
        abuf4[0][tid - 132] = z;
        abuf4[1][tid - 132] = z;
    }
    if (tid >= 160) asm volatile("cp.async.wait_group 0;\n");
    __syncthreads();

    // metadata: window idx 1..9 -> state s = 2k-8+idx; odd idx 3,5,7,9 = labels k-3..k
    const int k = tid;
    int vo9 = Cn-1, vo7 = Cn-1, vo5 = Cn-1, vo3 = Cn-1;
    float sk9 = 0.f, sk7 = 0.f, sk5 = 0.f, sk3 = 0.f;
    if (tid < 128) {
        vo9 = labs[k];
        if (k >= 1 && labs[k] != labs[k-1]) sk9 = 1.f;
        if (k >= 1) { vo7 = labs[k-1]; if (k >= 2 && labs[k-1] != labs[k-2]) sk7 = 1.f; }
        if (k >= 2) { vo5 = labs[k-2]; if (k >= 3 && labs[k-2] != labs[k-3]) sk5 = 1.f; }
        if (k >= 3) { vo3 = labs[k-3]; if (k >= 4 && labs[k-3] != labs[k-4]) sk3 = 1.f; }
    }

    // t = 0 init
    if (tid < 128) {
        float l8 = 0.f, l9 = 0.f; int e8 = ESENT, e9 = ESENT;
        if (k == 0) {
            packv(ring[0][Cn - 1] + EPSF, l8, e8);
            packv(ring[0][labs[0]] + EPSF, l9, e9);
        }
        float4 w = { l8, __int_as_float(e8), l9, __int_as_float(e9) };
        abuf4[0][k + 4] = w;
    }
    if (tid >= 128 && tid < 160) {
        const int l = tid - 128;
        const float4* r4 = (const float4*)ring[0];
        float4 x = r4[l], y = r4[l + 32];
        float part = ((x.x + x.y) + (x.z + x.w)) + ((y.x + y.y) + (y.z + y.w));
        #pragma unroll
        for (int o = 16; o; o >>= 1) part += __shfl_xor_sync(0xffffffffu, part, o);
        if (l == 0) sums[0] = part + (float)Cn * EPSF;
    }
    __syncthreads();

    // ---- main loop: 256 periods x 4 steps, zero MUFU ----
    int cur = 0;
    int s0 = 1;                            // (4p+1) % 12
    for (int p = 0; p < NPER; ++p) {
        if (tid < 128) {
            const float4* ap = abuf4[cur];
            const float4 q0 = ap[k],     q1 = ap[k + 1], q2 = ap[k + 2],
                         q3 = ap[k + 3], q4 = ap[k + 4];
            const int e1 = __float_as_int(q0.w), e2 = __float_as_int(q1.y),
                      e3 = __float_as_int(q1.w), e4 = __float_as_int(q2.y),
                      e5 = __float_as_int(q2.w), e6 = __float_as_int(q3.y),
                      e7 = __float_as_int(q3.w), e8 = __float_as_int(q4.y),
                      e9 = __float_as_int(q4.w);
            const int em = ::max(::max(::max(e1, e2), ::max(e3, e4)),
                                 ::max(::max(e5, e6), ::max(e7, ::max(e8, e9))));
            float A1 = sclin(q0.z, e1 - em), A2 = sclin(q1.x, e2 - em),
                  A3 = sclin(q1.z, e3 - em), A4 = sclin(q2.x, e4 - em),
                  A5 = sclin(q2.z, e5 - em), A6 = sclin(q3.x, e6 - em),
                  A7 = sclin(q3.z, e7 - em), A8 = sclin(q4.x, e8 - em),
                  A9 = sclin(q4.z, e9 - em);

            #pragma unroll
            for (int jj = 0; jj < 4; ++jj) {
                if (4 * p + 1 + jj < Tn) {
                    int sl = s0 + jj; if (sl >= RING) sl -= RING;
                    const float* r = ring[sl];
                    const float vb = r[Cn - 1] + EPSF;
                    {
                        const float v9 = r[vo9] + EPSF;
                        A9 = fmaf(sk9, A7, A9 + A8) * v9;
                        A8 = (A8 + A7) * vb;
                    }
                    if (jj <= 2) { const float v7 = r[vo7] + EPSF;
                                   A7 = fmaf(sk7, A5, A7 + A6) * v7; A6 = (A6 + A5) * vb; }
                    if (jj <= 1) { const float v5 = r[vo5] + EPSF;
                                   A5 = fmaf(sk5, A3, A5 + A4) * v5; A4 = (A4 + A3) * vb; }
                    if (jj == 0) { const float v3 = r[vo3] + EPSF;
                                   A3 = fmaf(sk3, A1, A3 + A2) * v3; A2 = (A2 + A1) * vb; }
                    if (k == 127) histL[4 * p + 1 + jj] = A9;
                }
            }
            if (k == 127) histM[p] = (float)em;

            // repack owned states (bit surgery, no MUFU)
            float l8n, l9n; int e8n, e9n;
            {
                const int b8 = __float_as_int(A8), ee8 = (b8 >> 23) & 255;
                if (ee8 == 0) { l8n = 0.f; e8n = ESENT; }
                else { l8n = A8 * __int_as_float((254 - ee8) << 23); e8n = em + ee8 - 127; }
                const int b9 = __float_as_int(A9), ee9 = (b9 >> 23) & 255;
                if (ee9 == 0) { l9n = 0.f; e9n = ESENT; }
                else { l9n = A9 * __int_as_float((254 - ee9) << 23); e9n = em + ee9 - 127; }
            }
            float4 w = { l8n, __int_as_float(e8n), l9n, __int_as_float(e9n) };
            abuf4[cur ^ 1][k + 4] = w;
        }
        else if (tid < 160) {              // denominator sums + blank capture, 4 rows
            const int l = tid - 128;
            float pr[4];
            #pragma unroll
            for (int rr = 0; rr < 4; ++rr) {
                const int t = 4 * p + 1 + rr;
                if (t < Tn) {
                    int sl = s0 + rr; if (sl >= RING) sl -= RING;
                    const float4* r4 = (const float4*)ring[sl];
                    float4 x = r4[l], y = r4[l + 32];
                    pr[rr] = ((x.x + x.y) + (x.z + x.w)) + ((y.x + y.y) + (y.z + y.w));
                    if (l == 31) vbh[t] = y.w;
                } else pr[rr] = 0.f;
            }
            #pragma unroll
            for (int o = 16; o; o >>= 1) {
                pr[0] += __shfl_xor_sync(0xffffffffu, pr[0], o);
                pr[1] += __shfl_xor_sync(0xffffffffu, pr[1], o);
                pr[2] += __shfl_xor_sync(0xffffffffu, pr[2], o);
                pr[3] += __shfl_xor_sync(0xffffffffu, pr[3], o);
            }
            if (l == 0) {
                #pragma unroll
                for (int rr = 0; rr < 4; ++rr) {
                    const int t = 4 * p + 1 + rr;
                    if (t < Tn) sums[t] = pr[rr] + (float)Cn * EPSF;
                }
            }
        }
        else {                             // loaders: rows 4p+9 .. 4p+12
            const int lt = tid - 160;
            int sw = s0 + 8; if (sw >= RING) sw -= RING;
            #pragma unroll
            for (int rr = 0; rr < 4; ++rr) {
                const int rt = 4 * p + 9 + rr;
                if (rt < Tn) {
                    int sl = sw + rr; if (sl >= RING) sl -= RING;
                    unsigned sa = (unsigned)__cvta_generic_to_shared(&ring[sl][lt * 4]);
                    const float* g = rowbase + (size_t)rt * Cn + lt * 4;
                    asm volatile("cp.async.cg.shared.global [%0], [%1], 16;\n" :: "r"(sa), "l"(g));
                }
            }
            asm volatile("cp.async.commit_group;\n");
            asm volatile("cp.async.wait_group 1;\n");
        }
        __syncthreads();
        cur ^= 1;
        s0 += 4; if (s0 >= RING) s0 -= RING;
    }

    // ==== epilogue (A256 reconstruction + D) ====
    if (tid < 128) {
        const int base = 8 * tid;
        float r = 0.f;
        #pragma unroll
        for (int j = 0; j < 8; ++j) {
            const int u = base + j;
            float x = (u == 0) ? 0.f : lg2f(vbh[u] + EPSF);
            r += x;
            pre[u] = r;
        }
        csum[tid] = r;
    }
    __syncthreads();

    if (tid < 32) {
        float c0 = csum[4*tid], c1 = csum[4*tid+1], c2 = csum[4*tid+2], c3 = csum[4*tid+3];
        float tot = ((c0 + c1) + (c2 + c3));
        float sc = tot;
        #pragma unroll
        for (int o = 1; o < 32; o <<= 1) {
            float v = __shfl_up_sync(0xffffffffu, sc, o);
            if (tid >= o) sc += v;
        }
        const float ex = sc - tot;
        coff[4*tid]   = ex;
        coff[4*tid+1] = ex + c0;
        coff[4*tid+2] = ex + c0 + c1;
        coff[4*tid+3] = ex + c0 + c1 + c2;
        if (tid == 31) PtotS = sc;
    }
    __syncthreads();

    const float Ptot = PtotS;
    float lm = -3.0e38f;
    for (int u = tid; u < Tn - 1; u += NTH) {
        const float hl = (u == 0) ? 0.f : histL[u];
        const float h = (u == 0 || hl <= 0.f) ? NEGF : histM[(u - 1) >> 2] + lg2f(hl);
        lm = fmaxf(lm, h + (Ptot - (coff[u >> 3] + pre[u])));
    }
    float d2 = 0.f;
    for (int t2 = tid; t2 < Tn; t2 += NTH) d2 += lg2f(sums[t2]);
    #pragma unroll
    for (int o = 16; o; o >>= 1) {
        lm = fmaxf(lm, __shfl_xor_sync(0xffffffffu, lm, o));
        d2 += __shfl_xor_sync(0xffffffffu, d2, o);
    }
    if ((tid & 31) == 0) { wredA[tid >> 5] = lm; wredB[tid >> 5] = d2; }
    __syncthreads();

    float M = wredA[0];
    #pragma unroll
    for (int w = 1; w < 7; ++w) M = fmaxf(M, wredA[w]);

    float se = 0.f;
    for (int u = tid; u < Tn - 1; u += NTH) {
        const float hl = (u == 0) ? 0.f : histL[u];
        const float h = (u == 0 || hl <= 0.f) ? NEGF : histM[(u - 1) >> 2] + lg2f(hl);
        se += ex2f(h + (Ptot - (coff[u >> 3] + pre[u])) - M);
    }
    #pragma unroll
    for (int o = 16; o; o >>= 1) se += __shfl_xor_sync(0xffffffffu, se, o);
    if ((tid & 31) == 0) wredC[tid >> 5] = se;
    __syncthreads();

    if (tid == 0) {
        float S = 0.f, D2 = 0.f;
        #pragma unroll
        for (int w = 0; w < 7; ++w) { S += wredC[w]; D2 += wredB[w]; }
        const float a256 = M + lg2f(S);
        const float4 qf = abuf4[cur][127 + 4];           // A255(T-1): (lin,e) in .z/.w
        const float x = (qf.z > 0.f)
                        ? (float)__float_as_int(qf.w) + lg2f(qf.z) : NEGF;
        const float m2 = fmaxf(x, a256);
        const float lse2 = m2 + lg2f(ex2f(x - m2) + ex2f(a256 - m2));
        out[b] = LN2F * (D2 - lse2);
    }
}

extern "C" void kernel_launch(void* const* d_in, const int* in_sizes, int n_in,
                              void* d_out, int out_size)
{
    int iy = (in_sizes[0] == Bn * Ln) ? 0 : 1;
    const void*  yt = d_in[iy];
    const float* yp = (const float*)d_in[1 - iy];
    ctc_kernel<<<Bn, NTH>>>(yt, yp, (float*)d_out);
}